// round 7
// baseline (speedup 1.0000x reference)
#include <cuda_runtime.h>
#include <cuda_bf16.h>

#define SEQ   4096
#define DH    2048
#define DOUT  1024
#define LN_EPS 1e-5f

// ---------------------------------------------------------------------------
// Scratch (__device__ globals; allocation-free rule)
// ---------------------------------------------------------------------------
__device__ __nv_bfloat16 g_ln   [(size_t)SEQ * DH];   // LN(gate) bf16 [n][d]
__device__ __nv_bfloat16 g_Wb   [(size_t)SEQ * SEQ];  // tril(W) bf16 [m][n]
__device__ float         g_gated[(size_t)SEQ * DH];   // gated, tf32-rounded [m][d]
__device__ float         g_pwt  [(size_t)DH * DOUT];  // proj_w, tf32-rounded [d][j]

// ---------------------------------------------------------------------------
// PTX helpers (compute_103-legal: ldmatrix / mma.sync / cp.async)
// ---------------------------------------------------------------------------
__device__ __forceinline__ unsigned smem_u32(const void* p) {
    unsigned a;
    asm("{ .reg .u64 t; cvta.to.shared.u64 t, %1; cvt.u32.u64 %0, t; }"
        : "=r"(a) : "l"(p));
    return a;
}

__device__ __forceinline__ void ldsm_x4(unsigned* r, unsigned addr) {
    asm volatile("ldmatrix.sync.aligned.m8n8.x4.shared.b16 {%0,%1,%2,%3}, [%4];"
                 : "=r"(r[0]), "=r"(r[1]), "=r"(r[2]), "=r"(r[3]) : "r"(addr));
}
__device__ __forceinline__ void ldsm_x4_t(unsigned* r, unsigned addr) {
    asm volatile("ldmatrix.sync.aligned.m8n8.x4.trans.shared.b16 {%0,%1,%2,%3}, [%4];"
                 : "=r"(r[0]), "=r"(r[1]), "=r"(r[2]), "=r"(r[3]) : "r"(addr));
}

__device__ __forceinline__ void mma16816(float* c, const unsigned* a,
                                         unsigned b0, unsigned b1) {
    asm volatile(
        "mma.sync.aligned.m16n8k16.row.col.f32.bf16.bf16.f32 "
        "{%0,%1,%2,%3}, {%4,%5,%6,%7}, {%8,%9}, {%0,%1,%2,%3};"
        : "+f"(c[0]), "+f"(c[1]), "+f"(c[2]), "+f"(c[3])
        : "r"(a[0]), "r"(a[1]), "r"(a[2]), "r"(a[3]), "r"(b0), "r"(b1));
}

__device__ __forceinline__ void mma1688_tf32(float* c, const unsigned* a,
                                             unsigned b0, unsigned b1) {
    asm volatile(
        "mma.sync.aligned.m16n8k8.row.col.f32.tf32.tf32.f32 "
        "{%0,%1,%2,%3}, {%4,%5,%6,%7}, {%8,%9}, {%0,%1,%2,%3};"
        : "+f"(c[0]), "+f"(c[1]), "+f"(c[2]), "+f"(c[3])
        : "r"(a[0]), "r"(a[1]), "r"(a[2]), "r"(a[3]), "r"(b0), "r"(b1));
}

__device__ __forceinline__ void cp16(unsigned dst, const void* src) {
    asm volatile("cp.async.cg.shared.global [%0], [%1], 16;"
                 :: "r"(dst), "l"(src) : "memory");
}
__device__ __forceinline__ void cp_commit() {
    asm volatile("cp.async.commit_group;" ::: "memory");
}
template <int N>
__device__ __forceinline__ void cp_wait() {
    asm volatile("cp.async.wait_group %0;" :: "n"(N) : "memory");
}

__device__ __forceinline__ unsigned pack2(float a, float b) {
    __nv_bfloat162 h = __floats2bfloat162_rn(a, b);
    return *reinterpret_cast<unsigned*>(&h);
}
__device__ __forceinline__ unsigned to_tf32(float f) {
    unsigned u;
    asm("cvt.rna.tf32.f32 %0, %1;" : "=r"(u) : "f"(f));
    return u;
}

// spatial smem strides (bf16 elems), conflict-free for ldmatrix
static constexpr int SP_AS_STR = 40;    // [128][40]
static constexpr int SP_BS_STR = 264;   // [32][264]  (BN=256 + 8 pad)
static constexpr int SP_AS_BUF = 128 * SP_AS_STR;
static constexpr int SP_BS_BUF = 32 * SP_BS_STR;
static constexpr int SP_STAGES = 3;

// proj smem strides (fp32 elems), conflict-free for LDS.32 fragment loads
static constexpr int PJ_AS_STR = 36;    // [128][36]
static constexpr int PJ_BS_STR = 136;   // [32][136]
static constexpr int PJ_AS_BUF = 128 * PJ_AS_STR;
static constexpr int PJ_BS_BUF = 32 * PJ_BS_STR;
static constexpr int PJ_STAGES = 3;

// ---------------------------------------------------------------------------
// Kernel 1: LayerNorm (scale only) of gate half -> bf16 g_ln[n][d]
// ---------------------------------------------------------------------------
__global__ __launch_bounds__(256) void ln_kernel(const float* __restrict__ x,
                                                 const float* __restrict__ ln_scale)
{
    const int row = blockIdx.x;
    const int t   = threadIdx.x;
    const float* g = x + (size_t)row * (2 * DH) + DH;

    float v[8];
    float sum = 0.f, sumsq = 0.f;
#pragma unroll
    for (int i = 0; i < 8; i++) {
        float val = g[t + i * 256];
        v[i] = val; sum += val; sumsq += val * val;
    }
    __shared__ float s1[8], s2[8];
#pragma unroll
    for (int o = 16; o > 0; o >>= 1) {
        sum   += __shfl_xor_sync(0xFFFFFFFFu, sum, o);
        sumsq += __shfl_xor_sync(0xFFFFFFFFu, sumsq, o);
    }
    const int w = t >> 5, l = t & 31;
    if (l == 0) { s1[w] = sum; s2[w] = sumsq; }
    __syncthreads();
    if (w == 0) {
        sum   = (l < 8) ? s1[l] : 0.f;
        sumsq = (l < 8) ? s2[l] : 0.f;
#pragma unroll
        for (int o = 4; o > 0; o >>= 1) {
            sum   += __shfl_xor_sync(0xFFFFFFFFu, sum, o);
            sumsq += __shfl_xor_sync(0xFFFFFFFFu, sumsq, o);
        }
        if (l == 0) { s1[0] = sum; s2[0] = sumsq; }
    }
    __syncthreads();
    const float mean = s1[0] * (1.0f / DH);
    const float var  = s2[0] * (1.0f / DH) - mean * mean;
    const float inv  = rsqrtf(var + LN_EPS);
#pragma unroll
    for (int i = 0; i < 8; i++) {
        const int j = t + i * 256;
        g_ln[(size_t)row * DH + j] =
            __float2bfloat16_rn((v[i] - mean) * inv * ln_scale[j]);
    }
}

// ---------------------------------------------------------------------------
// Kernel 2: round proj_w to tf32 (same [d][j] layout)
// ---------------------------------------------------------------------------
__global__ __launch_bounds__(256) void pw_cvt_kernel(const float* __restrict__ pw)
{
    const size_t i = ((size_t)blockIdx.x * 256 + threadIdx.x) * 4;
    float4 v = *(const float4*)(pw + i);
    uint4 u = make_uint4(to_tf32(v.x), to_tf32(v.y), to_tf32(v.z), to_tf32(v.w));
    *(uint4*)(g_pwt + i) = u;
}

// ---------------------------------------------------------------------------
// Kernel 2b: W fp32 -> tril-masked bf16 (only cols < (row|127)+1 are ever read)
// ---------------------------------------------------------------------------
__global__ __launch_bounds__(256) void w_cvt_kernel(const float* __restrict__ W)
{
    const int row   = blockIdx.x;
    const int ncols = (row & ~127) + 128;      // read extent for this row-block
    const float* src = W + (size_t)row * SEQ;
    __nv_bfloat16* dst = g_Wb + (size_t)row * SEQ;

    for (int c = threadIdx.x * 8; c < ncols; c += 256 * 8) {
        float4 f0 = *(const float4*)(src + c);
        float4 f1 = *(const float4*)(src + c + 4);
        if (c + 7 > row) {                     // diagonal region: mask n > m
            float* e0 = (float*)&f0;
            float* e1 = (float*)&f1;
#pragma unroll
            for (int q = 0; q < 4; q++) {
                if (c + q > row)     e0[q] = 0.f;
                if (c + 4 + q > row) e1[q] = 0.f;
            }
        }
        *(uint4*)(dst + c) = make_uint4(pack2(f0.x, f0.y), pack2(f0.z, f0.w),
                                        pack2(f1.x, f1.y), pack2(f1.z, f1.w));
    }
}

// ---------------------------------------------------------------------------
// Kernel 3: spatial mixing (HMMA bf16, 3-stage cp.async).
// BM=128 BN=256 BK=32, 512 thr.
// C[m][d] = sum_{n<=m} Wb[m][n]*g_ln[n][d]; epi: g_gated = tf32(xh*(C+sb[m]))
// ---------------------------------------------------------------------------
__global__ __launch_bounds__(512) void spatial_kernel(const float* __restrict__ x,
                                                      const float* __restrict__ sb)
{
    extern __shared__ __nv_bfloat16 sm[];
    __nv_bfloat16* As = sm;                            // [S][128][40]
    __nv_bfloat16* Bs = sm + SP_STAGES * SP_AS_BUF;    // [S][32][264]

    const int tid  = threadIdx.x;
    const int lane = tid & 31;
    const int wid  = tid >> 5;
    const int ntile = blockIdx.x & 7;
    const int mtile = 31 - (blockIdx.x >> 3);   // heavy tiles first
    const int m0 = mtile * 128;
    const int n0 = ntile * 256;
    const int wm = wid & 3;      // 4 warps along M (32 rows)
    const int wn = wid >> 2;     // 4 warps along N (64 cols)

    float acc[2][8][4];
#pragma unroll
    for (int i = 0; i < 2; i++)
#pragma unroll
        for (int j = 0; j < 8; j++)
#pragma unroll
            for (int q = 0; q < 4; q++) acc[i][j][q] = 0.f;

    // A: 512 thr x 16B = full 128x32 bf16 tile
    const int ra = tid >> 2;             // 0..127
    const int ca = (tid & 3) * 8;        // 0,8,16,24

    auto cpA = [&](int buf, int k0) {
        cp16(smem_u32(As + buf * SP_AS_BUF + ra * SP_AS_STR + ca),
             g_Wb + (size_t)(m0 + ra) * SEQ + k0 + ca);
    };
    auto cpB = [&](int buf, int k0) {
#pragma unroll
        for (int it = 0; it < 2; it++) {
            const int idx = tid + it * 512;
            const int r   = idx >> 5;            // 0..31 (k)
            const int c8  = (idx & 31) * 8;      // 0..248 (n)
            cp16(smem_u32(Bs + buf * SP_BS_BUF + r * SP_BS_STR + c8),
                 g_ln + (size_t)(k0 + r) * DH + n0 + c8);
        }
    };
    auto compute = [&](int buf) {
        const __nv_bfloat16* A0 = As + buf * SP_AS_BUF;
        const __nv_bfloat16* B0 = Bs + buf * SP_BS_BUF;
#pragma unroll
        for (int ks = 0; ks < 2; ks++) {
            unsigned a[2][4], b[4][4];
#pragma unroll
            for (int am = 0; am < 2; am++)
                ldsm_x4(a[am], smem_u32(A0 + (wm * 32 + am * 16 + (lane & 15)) * SP_AS_STR
                                           + ks * 16 + (lane >> 4) * 8));
#pragma unroll
            for (int p = 0; p < 4; p++)
                ldsm_x4_t(b[p], smem_u32(B0 + (ks * 16 + (lane & 15)) * SP_BS_STR
                                            + wn * 64 + p * 16 + (lane >> 4) * 8));
#pragma unroll
            for (int am = 0; am < 2; am++)
#pragma unroll
                for (int p = 0; p < 4; p++) {
                    mma16816(acc[am][2 * p + 0], a[am], b[p][0], b[p][1]);
                    mma16816(acc[am][2 * p + 1], a[am], b[p][2], b[p][3]);
                }
        }
    };

    const int nch = 4 * mtile + 4;       // kend = m0+128

    // prologue: stages 0..S-2
#pragma unroll
    for (int s = 0; s < SP_STAGES - 1; s++) {
        if (s < nch) { cpA(s, s * 32); cpB(s, s * 32); }
        cp_commit();
    }
    // mainloop
    for (int i = 0; i < nch; i++) {
        cp_wait<SP_STAGES - 2>();
        __syncthreads();
        const int nx = i + SP_STAGES - 1;
        if (nx < nch) { cpA(nx % SP_STAGES, nx * 32); cpB(nx % SP_STAGES, nx * 32); }
        cp_commit();
        compute(i % SP_STAGES);
    }

    // epilogue: g_gated = tf32( xh * (acc + sb[m]) )
#pragma unroll
    for (int am = 0; am < 2; am++) {
        const int gmb = m0 + wm * 32 + am * 16 + (lane >> 2);
#pragma unroll
        for (int nb = 0; nb < 8; nb++) {
            const int gc = n0 + wn * 64 + nb * 8 + (lane & 3) * 2;
#pragma unroll
            for (int half = 0; half < 2; half++) {
                const int gm = gmb + half * 8;
                const float bias = sb[gm];
                const float2 xv = *(const float2*)(x + (size_t)gm * SEQ + gc);
                float v0 = xv.x * (acc[am][nb][half * 2 + 0] + bias);
                float v1 = xv.y * (acc[am][nb][half * 2 + 1] + bias);
                *(uint2*)(g_gated + (size_t)gm * DH + gc) =
                    make_uint2(to_tf32(v0), to_tf32(v1));
            }
        }
    }
}

// ---------------------------------------------------------------------------
// Kernel 4: projection (tf32 m16n8k8, 3-stage cp.async). BM=128 BN=128 BK=32.
// out = g_gated @ g_pwt + pb
// ---------------------------------------------------------------------------
__global__ __launch_bounds__(256, 2) void proj_kernel(const float* __restrict__ pb,
                                                      float* __restrict__ out)
{
    extern __shared__ float smf[];
    float* Af = smf;                           // [S][128][36]
    float* Bf = smf + PJ_STAGES * PJ_AS_BUF;   // [S][32][136]

    const int tid  = threadIdx.x;
    const int lane = tid & 31;
    const int wid  = tid >> 5;
    const int ntile = blockIdx.x & 7;
    const int mtile = blockIdx.x >> 3;
    const int m0 = mtile * 128;
    const int n0 = ntile * 128;
    const int wm = wid & 3;      // 4 warps M (32 rows)
    const int wn = wid >> 2;     // 2 warps N (64 cols)
    const int g = lane >> 2;     // groupID 0..7
    const int t = lane & 3;      // thread-in-group

    float acc[2][8][4];
#pragma unroll
    for (int i = 0; i < 2; i++)
#pragma unroll
        for (int j = 0; j < 8; j++)
#pragma unroll
            for (int q = 0; q < 4; q++) acc[i][j][q] = 0.f;

    auto cpStage = [&](int buf, int k0) {
#pragma unroll
        for (int it = 0; it < 4; it++) {
            const int idx = tid + it * 256;
            {   // A tile [128][32] fp32
                const int r = idx >> 3;
                const int c = (idx & 7) * 4;
                cp16(smem_u32(Af + buf * PJ_AS_BUF + r * PJ_AS_STR + c),
                     g_gated + (size_t)(m0 + r) * DH + k0 + c);
            }
            {   // B tile [32][128] fp32
                const int r = idx >> 5;
                const int c = (idx & 31) * 4;
                cp16(smem_u32(Bf + buf * PJ_BS_BUF + r * PJ_BS_STR + c),
                     g_pwt + (size_t)(k0 + r) * DOUT + n0 + c);
            }
        }
    };
    auto compute = [&](int buf) {
        const float* A0 = Af + buf * PJ_AS_BUF;
        const float* B0 = Bf + buf * PJ_BS_BUF;
#pragma unroll
        for (int ks = 0; ks < 4; ks++) {
            unsigned a[2][4], b[8][2];
#pragma unroll
            for (int mb = 0; mb < 2; mb++) {
                const float* Ap = A0 + (wm * 32 + mb * 16) * PJ_AS_STR + ks * 8;
                a[mb][0] = __float_as_uint(Ap[(g    ) * PJ_AS_STR + t    ]);
                a[mb][1] = __float_as_uint(Ap[(g + 8) * PJ_AS_STR + t    ]);
                a[mb][2] = __float_as_uint(Ap[(g    ) * PJ_AS_STR + t + 4]);
                a[mb][3] = __float_as_uint(Ap[(g + 8) * PJ_AS_STR + t + 4]);
            }
#pragma unroll
            for (int nb = 0; nb < 8; nb++) {
                const float* Bp = B0 + ks * 8 * PJ_BS_STR + wn * 64 + nb * 8 + g;
                b[nb][0] = __float_as_uint(Bp[ t      * PJ_BS_STR]);
                b[nb][1] = __float_as_uint(Bp[(t + 4) * PJ_BS_STR]);
            }
#pragma unroll
            for (int mb = 0; mb < 2; mb++)
#pragma unroll
                for (int nb = 0; nb < 8; nb++)
                    mma1688_tf32(acc[mb][nb], a[mb], b[nb][0], b[nb][1]);
        }
    };

    const int nch = DH / 32;   // 64

    // prologue
#pragma unroll
    for (int s = 0; s < PJ_STAGES - 1; s++) {
        cpStage(s, s * 32);
        cp_commit();
    }
    // mainloop
    for (int i = 0; i < nch; i++) {
        cp_wait<PJ_STAGES - 2>();
        __syncthreads();
        const int nx = i + PJ_STAGES - 1;
        if (nx < nch) cpStage(nx % PJ_STAGES, nx * 32);
        cp_commit();
        compute(i % PJ_STAGES);
    }

    // epilogue: + pb
#pragma unroll
    for (int mb = 0; mb < 2; mb++) {
        const int gmb = m0 + wm * 32 + mb * 16 + g;
#pragma unroll
        for (int nb = 0; nb < 8; nb++) {
            const int gc = n0 + wn * 64 + nb * 8 + t * 2;
            const float2 bias = *(const float2*)(pb + gc);
#pragma unroll
            for (int half = 0; half < 2; half++) {
                const int gm = gmb + half * 8;
                float2 o;
                o.x = acc[mb][nb][half * 2 + 0] + bias.x;
                o.y = acc[mb][nb][half * 2 + 1] + bias.y;
                *(float2*)(out + (size_t)gm * DOUT + gc) = o;
            }
        }
    }
}

// ---------------------------------------------------------------------------
extern "C" void kernel_launch(void* const* d_in, const int* in_sizes, int n_in,
                              void* d_out, int out_size)
{
    const float* x        = (const float*)d_in[0];  // (4096, 4096)
    const float* ln_scale = (const float*)d_in[1];  // (2048,)
    const float* W        = (const float*)d_in[2];  // (4096, 4096)
    const float* sb       = (const float*)d_in[3];  // (4096, 1)
    const float* pw       = (const float*)d_in[4];  // (2048, 1024)
    const float* pb       = (const float*)d_in[5];  // (1024,)
    float* out            = (float*)d_out;          // (4096, 1024)

    const int SP_SMEM = SP_STAGES * (SP_AS_BUF + SP_BS_BUF) * 2;  // 81408 B
    const int PJ_SMEM = PJ_STAGES * (PJ_AS_BUF + PJ_BS_BUF) * 4;  // 107520 B
    cudaFuncSetAttribute(spatial_kernel,
                         cudaFuncAttributeMaxDynamicSharedMemorySize, SP_SMEM);
    cudaFuncSetAttribute(proj_kernel,
                         cudaFuncAttributeMaxDynamicSharedMemorySize, PJ_SMEM);

    ln_kernel<<<SEQ, 256>>>(x, ln_scale);
    w_cvt_kernel<<<SEQ, 256>>>(W);
    pw_cvt_kernel<<<(DH * DOUT) / (256 * 4), 256>>>(pw);
    spatial_kernel<<<256, 512, SP_SMEM>>>(x, sb);
    proj_kernel<<<256, 256, PJ_SMEM>>>(pb, out);
}

// round 12
// speedup vs baseline: 1.0737x; 1.0737x over previous
#include <cuda_runtime.h>
#include <cuda_bf16.h>

#define SEQ   4096
#define DH    2048
#define DOUT  1024
#define LN_EPS 1e-5f

// ---------------------------------------------------------------------------
// Scratch (__device__ globals; allocation-free rule)
// ---------------------------------------------------------------------------
__device__ __nv_bfloat16 g_ln   [(size_t)SEQ * DH];   // LN(gate) bf16 [n][d]
__device__ __nv_bfloat16 g_Wb   [(size_t)SEQ * SEQ];  // tril(W) bf16 [m][n]
__device__ float         g_gated[(size_t)SEQ * DH];   // gated, tf32-rounded [m][d]
__device__ float         g_pwt  [(size_t)DH * DOUT];  // proj_w, tf32-rounded [d][j]

// ---------------------------------------------------------------------------
// PTX helpers (compute_103-legal: ldmatrix / mma.sync / cp.async)
// ---------------------------------------------------------------------------
__device__ __forceinline__ unsigned smem_u32(const void* p) {
    unsigned a;
    asm("{ .reg .u64 t; cvta.to.shared.u64 t, %1; cvt.u32.u64 %0, t; }"
        : "=r"(a) : "l"(p));
    return a;
}

__device__ __forceinline__ void ldsm_x4(unsigned* r, unsigned addr) {
    asm volatile("ldmatrix.sync.aligned.m8n8.x4.shared.b16 {%0,%1,%2,%3}, [%4];"
                 : "=r"(r[0]), "=r"(r[1]), "=r"(r[2]), "=r"(r[3]) : "r"(addr));
}
__device__ __forceinline__ void ldsm_x4_t(unsigned* r, unsigned addr) {
    asm volatile("ldmatrix.sync.aligned.m8n8.x4.trans.shared.b16 {%0,%1,%2,%3}, [%4];"
                 : "=r"(r[0]), "=r"(r[1]), "=r"(r[2]), "=r"(r[3]) : "r"(addr));
}

__device__ __forceinline__ void mma16816(float* c, const unsigned* a,
                                         unsigned b0, unsigned b1) {
    asm volatile(
        "mma.sync.aligned.m16n8k16.row.col.f32.bf16.bf16.f32 "
        "{%0,%1,%2,%3}, {%4,%5,%6,%7}, {%8,%9}, {%0,%1,%2,%3};"
        : "+f"(c[0]), "+f"(c[1]), "+f"(c[2]), "+f"(c[3])
        : "r"(a[0]), "r"(a[1]), "r"(a[2]), "r"(a[3]), "r"(b0), "r"(b1));
}

__device__ __forceinline__ void mma1688_tf32(float* c, const unsigned* a,
                                             unsigned b0, unsigned b1) {
    asm volatile(
        "mma.sync.aligned.m16n8k8.row.col.f32.tf32.tf32.f32 "
        "{%0,%1,%2,%3}, {%4,%5,%6,%7}, {%8,%9}, {%0,%1,%2,%3};"
        : "+f"(c[0]), "+f"(c[1]), "+f"(c[2]), "+f"(c[3])
        : "r"(a[0]), "r"(a[1]), "r"(a[2]), "r"(a[3]), "r"(b0), "r"(b1));
}

__device__ __forceinline__ void cp16(unsigned dst, const void* src) {
    asm volatile("cp.async.cg.shared.global [%0], [%1], 16;"
                 :: "r"(dst), "l"(src) : "memory");
}
__device__ __forceinline__ void cp_commit() {
    asm volatile("cp.async.commit_group;" ::: "memory");
}
template <int N>
__device__ __forceinline__ void cp_wait() {
    asm volatile("cp.async.wait_group %0;" :: "n"(N) : "memory");
}

__device__ __forceinline__ unsigned pack2(float a, float b) {
    __nv_bfloat162 h = __floats2bfloat162_rn(a, b);
    return *reinterpret_cast<unsigned*>(&h);
}
__device__ __forceinline__ unsigned to_tf32(float f) {
    unsigned u;
    asm("cvt.rna.tf32.f32 %0, %1;" : "=r"(u) : "f"(f));
    return u;
}

// spatial smem strides (bf16 elems), conflict-free for ldmatrix
static constexpr int SP_AS_STR = 40;    // [128][40]
static constexpr int SP_BS_STR = 136;   // [32][136]
static constexpr int SP_AS_BUF = 128 * SP_AS_STR;
static constexpr int SP_BS_BUF = 32 * SP_BS_STR;
static constexpr int SP_STAGES = 3;

// proj smem strides (fp32 elems), conflict-free for LDS.32 fragment loads
static constexpr int PJ_AS_STR = 36;    // [128][36]
static constexpr int PJ_BS_STR = 264;   // [32][264]  (BN=256 + 8 pad)
static constexpr int PJ_AS_BUF = 128 * PJ_AS_STR;
static constexpr int PJ_BS_BUF = 32 * PJ_BS_STR;
static constexpr int PJ_STAGES = 3;

// ---------------------------------------------------------------------------
// Kernel 1: LayerNorm (scale only) of gate half -> bf16 g_ln[n][d]
// ---------------------------------------------------------------------------
__global__ __launch_bounds__(256) void ln_kernel(const float* __restrict__ x,
                                                 const float* __restrict__ ln_scale)
{
    const int row = blockIdx.x;
    const int t   = threadIdx.x;
    const float* g = x + (size_t)row * (2 * DH) + DH;

    float v[8];
    float sum = 0.f, sumsq = 0.f;
#pragma unroll
    for (int i = 0; i < 8; i++) {
        float val = g[t + i * 256];
        v[i] = val; sum += val; sumsq += val * val;
    }
    __shared__ float s1[8], s2[8];
#pragma unroll
    for (int o = 16; o > 0; o >>= 1) {
        sum   += __shfl_xor_sync(0xFFFFFFFFu, sum, o);
        sumsq += __shfl_xor_sync(0xFFFFFFFFu, sumsq, o);
    }
    const int w = t >> 5, l = t & 31;
    if (l == 0) { s1[w] = sum; s2[w] = sumsq; }
    __syncthreads();
    if (w == 0) {
        sum   = (l < 8) ? s1[l] : 0.f;
        sumsq = (l < 8) ? s2[l] : 0.f;
#pragma unroll
        for (int o = 4; o > 0; o >>= 1) {
            sum   += __shfl_xor_sync(0xFFFFFFFFu, sum, o);
            sumsq += __shfl_xor_sync(0xFFFFFFFFu, sumsq, o);
        }
        if (l == 0) { s1[0] = sum; s2[0] = sumsq; }
    }
    __syncthreads();
    const float mean = s1[0] * (1.0f / DH);
    const float var  = s2[0] * (1.0f / DH) - mean * mean;
    const float inv  = rsqrtf(var + LN_EPS);
#pragma unroll
    for (int i = 0; i < 8; i++) {
        const int j = t + i * 256;
        g_ln[(size_t)row * DH + j] =
            __float2bfloat16_rn((v[i] - mean) * inv * ln_scale[j]);
    }
}

// ---------------------------------------------------------------------------
// Kernel 2: round proj_w to tf32 (same [d][j] layout)
// ---------------------------------------------------------------------------
__global__ __launch_bounds__(256) void pw_cvt_kernel(const float* __restrict__ pw)
{
    const size_t i = ((size_t)blockIdx.x * 256 + threadIdx.x) * 4;
    float4 v = *(const float4*)(pw + i);
    uint4 u = make_uint4(to_tf32(v.x), to_tf32(v.y), to_tf32(v.z), to_tf32(v.w));
    *(uint4*)(g_pwt + i) = u;
}

// ---------------------------------------------------------------------------
// Kernel 2b: W fp32 -> tril-masked bf16 (only cols < (row|127)+1 are ever read)
// ---------------------------------------------------------------------------
__global__ __launch_bounds__(256) void w_cvt_kernel(const float* __restrict__ W)
{
    const int row   = blockIdx.x;
    const int ncols = (row & ~127) + 128;
    const float* src = W + (size_t)row * SEQ;
    __nv_bfloat16* dst = g_Wb + (size_t)row * SEQ;

    for (int c = threadIdx.x * 8; c < ncols; c += 256 * 8) {
        float4 f0 = *(const float4*)(src + c);
        float4 f1 = *(const float4*)(src + c + 4);
        if (c + 7 > row) {
            float* e0 = (float*)&f0;
            float* e1 = (float*)&f1;
#pragma unroll
            for (int q = 0; q < 4; q++) {
                if (c + q > row)     e0[q] = 0.f;
                if (c + 4 + q > row) e1[q] = 0.f;
            }
        }
        *(uint4*)(dst + c) = make_uint4(pack2(f0.x, f0.y), pack2(f0.z, f0.w),
                                        pack2(f1.x, f1.y), pack2(f1.z, f1.w));
    }
}

// ---------------------------------------------------------------------------
// Kernel 3: spatial mixing (HMMA bf16, 3-stage cp.async).
// BM=128 BN=128 BK=32, 256 thr, 2 CTAs/SM, warp tile 64x32 (2x4 warps).
// ---------------------------------------------------------------------------
__global__ __launch_bounds__(256, 2) void spatial_kernel(const float* __restrict__ x,
                                                         const float* __restrict__ sb)
{
    extern __shared__ __nv_bfloat16 sm[];
    __nv_bfloat16* As = sm;                            // [S][128][40]
    __nv_bfloat16* Bs = sm + SP_STAGES * SP_AS_BUF;    // [S][32][136]

    const int tid  = threadIdx.x;
    const int lane = tid & 31;
    const int wid  = tid >> 5;
    const int ntile = blockIdx.x & 15;
    const int mtile = 31 - (blockIdx.x >> 4);   // heavy tiles first
    const int m0 = mtile * 128;
    const int n0 = ntile * 128;
    const int wm = wid & 1;      // 2 warps along M (64 rows)
    const int wn = wid >> 1;     // 4 warps along N (32 cols)

    float acc[4][4][4];
#pragma unroll
    for (int i = 0; i < 4; i++)
#pragma unroll
        for (int j = 0; j < 4; j++)
#pragma unroll
            for (int q = 0; q < 4; q++) acc[i][j][q] = 0.f;

    // A: 128x32 bf16 tile, 2 cp16 per thread
    const int ra = tid >> 1;             // 0..127
    const int ca = (tid & 1) * 16;       // 0,16

    auto cpA = [&](int buf, int k0) {
        const __nv_bfloat16* src = g_Wb + (size_t)(m0 + ra) * SEQ + k0 + ca;
        __nv_bfloat16* dst = As + buf * SP_AS_BUF + ra * SP_AS_STR + ca;
        cp16(smem_u32(dst),     src);
        cp16(smem_u32(dst + 8), src + 8);
    };
    auto cpB = [&](int buf, int k0) {
#pragma unroll
        for (int it = 0; it < 2; it++) {
            const int idx = tid + it * 256;
            const int r   = idx >> 4;            // 0..31 (k)
            const int c8  = (idx & 15) * 8;      // 0..120 (n)
            cp16(smem_u32(Bs + buf * SP_BS_BUF + r * SP_BS_STR + c8),
                 g_ln + (size_t)(k0 + r) * DH + n0 + c8);
        }
    };
    auto compute = [&](int buf) {
        const __nv_bfloat16* A0 = As + buf * SP_AS_BUF;
        const __nv_bfloat16* B0 = Bs + buf * SP_BS_BUF;
#pragma unroll
        for (int ks = 0; ks < 2; ks++) {
            unsigned a[4][4], b[2][4];
#pragma unroll
            for (int mb = 0; mb < 4; mb++)
                ldsm_x4(a[mb], smem_u32(A0 + (wm * 64 + mb * 16 + (lane & 15)) * SP_AS_STR
                                           + ks * 16 + (lane >> 4) * 8));
#pragma unroll
            for (int p = 0; p < 2; p++)
                ldsm_x4_t(b[p], smem_u32(B0 + (ks * 16 + (lane & 15)) * SP_BS_STR
                                            + wn * 32 + p * 16 + (lane >> 4) * 8));
#pragma unroll
            for (int mb = 0; mb < 4; mb++)
#pragma unroll
                for (int p = 0; p < 2; p++) {
                    mma16816(acc[mb][2 * p + 0], a[mb], b[p][0], b[p][1]);
                    mma16816(acc[mb][2 * p + 1], a[mb], b[p][2], b[p][3]);
                }
        }
    };

    const int nch = 4 * mtile + 4;       // kend = m0+128

#pragma unroll
    for (int s = 0; s < SP_STAGES - 1; s++) {
        if (s < nch) { cpA(s, s * 32); cpB(s, s * 32); }
        cp_commit();
    }
    for (int i = 0; i < nch; i++) {
        cp_wait<SP_STAGES - 2>();
        __syncthreads();
        const int nx = i + SP_STAGES - 1;
        if (nx < nch) { cpA(nx % SP_STAGES, nx * 32); cpB(nx % SP_STAGES, nx * 32); }
        cp_commit();
        compute(i % SP_STAGES);
    }

    // epilogue: g_gated = tf32( xh * (acc + sb[m]) )
#pragma unroll
    for (int mb = 0; mb < 4; mb++) {
        const int gmb = m0 + wm * 64 + mb * 16 + (lane >> 2);
#pragma unroll
        for (int nb = 0; nb < 4; nb++) {
            const int gc = n0 + wn * 32 + nb * 8 + (lane & 3) * 2;
#pragma unroll
            for (int half = 0; half < 2; half++) {
                const int gm = gmb + half * 8;
                const float bias = sb[gm];
                const float2 xv = *(const float2*)(x + (size_t)gm * SEQ + gc);
                float v0 = xv.x * (acc[mb][nb][half * 2 + 0] + bias);
                float v1 = xv.y * (acc[mb][nb][half * 2 + 1] + bias);
                *(uint2*)(g_gated + (size_t)gm * DH + gc) =
                    make_uint2(to_tf32(v0), to_tf32(v1));
            }
        }
    }
}

// ---------------------------------------------------------------------------
// Kernel 4: projection (tf32 m16n8k8, 3-stage cp.async).
// BM=128 BN=256 BK=32, 256 thr, warp tile 64x64 (2x4 warps).
// out = g_gated @ g_pwt + pb  — grid 128 CTAs = one wave.
// ---------------------------------------------------------------------------
__global__ __launch_bounds__(256) void proj_kernel(const float* __restrict__ pb,
                                                   float* __restrict__ out)
{
    extern __shared__ float smf[];
    float* Af = smf;                           // [S][128][36]
    float* Bf = smf + PJ_STAGES * PJ_AS_BUF;   // [S][32][264]

    const int tid  = threadIdx.x;
    const int lane = tid & 31;
    const int wid  = tid >> 5;
    const int ntile = blockIdx.x & 3;
    const int mtile = blockIdx.x >> 2;
    const int m0 = mtile * 128;
    const int n0 = ntile * 256;
    const int wm = wid & 1;      // 2 warps M (64 rows)
    const int wn = wid >> 1;     // 4 warps N (64 cols)
    const int g = lane >> 2;     // groupID 0..7
    const int t = lane & 3;      // thread-in-group

    float acc[4][8][4];
#pragma unroll
    for (int i = 0; i < 4; i++)
#pragma unroll
        for (int j = 0; j < 8; j++)
#pragma unroll
            for (int q = 0; q < 4; q++) acc[i][j][q] = 0.f;

    auto cpStage = [&](int buf, int k0) {
#pragma unroll
        for (int it = 0; it < 4; it++) {       // A tile [128][32] fp32
            const int idx = tid + it * 256;
            const int r = idx >> 3;
            const int c = (idx & 7) * 4;
            cp16(smem_u32(Af + buf * PJ_AS_BUF + r * PJ_AS_STR + c),
                 g_gated + (size_t)(m0 + r) * DH + k0 + c);
        }
#pragma unroll
        for (int it = 0; it < 8; it++) {       // B tile [32][256] fp32
            const int idx = tid + it * 256;
            const int r = idx >> 6;
            const int c = (idx & 63) * 4;
            cp16(smem_u32(Bf + buf * PJ_BS_BUF + r * PJ_BS_STR + c),
                 g_pwt + (size_t)(k0 + r) * DOUT + n0 + c);
        }
    };
    auto compute = [&](int buf) {
        const float* A0 = Af + buf * PJ_AS_BUF;
        const float* B0 = Bf + buf * PJ_BS_BUF;
#pragma unroll
        for (int ks = 0; ks < 4; ks++) {
            unsigned a[4][4], b[8][2];
#pragma unroll
            for (int mb = 0; mb < 4; mb++) {
                const float* Ap = A0 + (wm * 64 + mb * 16) * PJ_AS_STR + ks * 8;
                a[mb][0] = __float_as_uint(Ap[(g    ) * PJ_AS_STR + t    ]);
                a[mb][1] = __float_as_uint(Ap[(g + 8) * PJ_AS_STR + t    ]);
                a[mb][2] = __float_as_uint(Ap[(g    ) * PJ_AS_STR + t + 4]);
                a[mb][3] = __float_as_uint(Ap[(g + 8) * PJ_AS_STR + t + 4]);
            }
#pragma unroll
            for (int nb = 0; nb < 8; nb++) {
                const float* Bp = B0 + ks * 8 * PJ_BS_STR + wn * 64 + nb * 8 + g;
                b[nb][0] = __float_as_uint(Bp[ t      * PJ_BS_STR]);
                b[nb][1] = __float_as_uint(Bp[(t + 4) * PJ_BS_STR]);
            }
#pragma unroll
            for (int mb = 0; mb < 4; mb++)
#pragma unroll
                for (int nb = 0; nb < 8; nb++)
                    mma1688_tf32(acc[mb][nb], a[mb], b[nb][0], b[nb][1]);
        }
    };

    const int nch = DH / 32;   // 64

#pragma unroll
    for (int s = 0; s < PJ_STAGES - 1; s++) {
        cpStage(s, s * 32);
        cp_commit();
    }
    for (int i = 0; i < nch; i++) {
        cp_wait<PJ_STAGES - 2>();
        __syncthreads();
        const int nx = i + PJ_STAGES - 1;
        if (nx < nch) cpStage(nx % PJ_STAGES, nx * 32);
        cp_commit();
        compute(i % PJ_STAGES);
    }

    // epilogue: + pb
#pragma unroll
    for (int mb = 0; mb < 4; mb++) {
        const int gmb = m0 + wm * 64 + mb * 16 + g;
#pragma unroll
        for (int nb = 0; nb < 8; nb++) {
            const int gc = n0 + wn * 64 + nb * 8 + t * 2;
            const float2 bias = *(const float2*)(pb + gc);
#pragma unroll
            for (int half = 0; half < 2; half++) {
                const int gm = gmb + half * 8;
                float2 o;
                o.x = acc[mb][nb][half * 2 + 0] + bias.x;
                o.y = acc[mb][nb][half * 2 + 1] + bias.y;
                *(float2*)(out + (size_t)gm * DOUT + gc) = o;
            }
        }
    }
}

// ---------------------------------------------------------------------------
extern "C" void kernel_launch(void* const* d_in, const int* in_sizes, int n_in,
                              void* d_out, int out_size)
{
    const float* x        = (const float*)d_in[0];  // (4096, 4096)
    const float* ln_scale = (const float*)d_in[1];  // (2048,)
    const float* W        = (const float*)d_in[2];  // (4096, 4096)
    const float* sb       = (const float*)d_in[3];  // (4096, 1)
    const float* pw       = (const float*)d_in[4];  // (2048, 1024)
    const float* pb       = (const float*)d_in[5];  // (1024,)
    float* out            = (float*)d_out;          // (4096, 1024)

    const int SP_SMEM = SP_STAGES * (SP_AS_BUF + SP_BS_BUF) * 2;  // 56832 B
    const int PJ_SMEM = PJ_STAGES * (PJ_AS_BUF + PJ_BS_BUF) * 4;  // 156672 B
    cudaFuncSetAttribute(spatial_kernel,
                         cudaFuncAttributeMaxDynamicSharedMemorySize, SP_SMEM);
    cudaFuncSetAttribute(proj_kernel,
                         cudaFuncAttributeMaxDynamicSharedMemorySize, PJ_SMEM);

    ln_kernel<<<SEQ, 256>>>(x, ln_scale);
    w_cvt_kernel<<<SEQ, 256>>>(W);
    pw_cvt_kernel<<<(DH * DOUT) / (256 * 4), 256>>>(pw);
    spatial_kernel<<<512, 256, SP_SMEM>>>(x, sb);
    proj_kernel<<<128, 256, PJ_SMEM>>>(pb, out);
}